// round 4
// baseline (speedup 1.0000x reference)
#include <cuda_runtime.h>
#include <cuda_bf16.h>
#include <math.h>

#define N_NODES 50000
#define N_EDGES 800000
#define HIDDEN  128
#define N_REL   64

// ---------------- device scratch (no dynamic allocation allowed) ----------------
__device__ float g_QKV[N_NODES * 384];     // q | k | v per node, stride 384
__device__ float g_AO[N_NODES * HIDDEN];   // attention output before Wo
__device__ float g_Bpack[128 * 384];       // [Wq_top | Wk_top | Wv]
__device__ float g_biasp[384];             // [cq | ck | bv]
__device__ int   g_cnt[N_NODES];
__device__ int   g_start[N_NODES + 1];
__device__ int   g_fill[N_NODES];
__device__ int2  g_sorted[N_EDGES];        // (src, type) sorted by dst

// ---------------- prep: pack B and fold query into bias ----------------
__global__ void prep_kernel(const float* __restrict__ qe,
                            const float* __restrict__ Wq, const float* __restrict__ bq,
                            const float* __restrict__ Wk, const float* __restrict__ bk,
                            const float* __restrict__ Wv, const float* __restrict__ bv) {
    int j = threadIdx.x;  // 0..383
    float c;
    if (j < 128) {
        c = bq[j];
        #pragma unroll 4
        for (int i = 0; i < 128; i++) c += qe[i] * Wq[(128 + i) * 128 + j];
        for (int i = 0; i < 128; i++) g_Bpack[i * 384 + j] = Wq[i * 128 + j];
    } else if (j < 256) {
        int jj = j - 128;
        c = bk[jj];
        #pragma unroll 4
        for (int i = 0; i < 128; i++) c += qe[i] * Wk[(128 + i) * 128 + jj];
        for (int i = 0; i < 128; i++) g_Bpack[i * 384 + j] = Wk[i * 128 + jj];
    } else {
        int jj = j - 256;
        c = bv[jj];
        for (int i = 0; i < 128; i++) g_Bpack[i * 384 + j] = Wv[i * 128 + jj];
    }
    g_biasp[j] = c;
}

// ---------------- generic fp32 GEMM: C[M,N] = A[M,128] @ B[128,N] + bias ----------------
// BM=128, BN=128, BK=32, 256 threads, 8x8 microtile per thread.
__global__ void gemm_kernel(const float* __restrict__ A, const float* __restrict__ B,
                            const float* __restrict__ bias, float* __restrict__ C,
                            int M, int N) {
    __shared__ float As[128][33];   // [m][k], padded
    __shared__ float Bs[32][128];   // [k][n]
    const int tid = threadIdx.x;
    const int tx = tid & 15;        // 0..15 -> 8 cols
    const int ty = tid >> 4;        // 0..15 -> 8 rows
    const int m0 = blockIdx.x * 128;
    const int n0 = blockIdx.y * 128;

    float acc[8][8];
    #pragma unroll
    for (int i = 0; i < 8; i++)
        #pragma unroll
        for (int j = 0; j < 8; j++) acc[i][j] = 0.f;

    for (int k0 = 0; k0 < 128; k0 += 32) {
        // load A tile 128x32 (float4, coalesced), store into As[m][k]
        #pragma unroll
        for (int it = 0; it < 4; it++) {
            int idx = tid + it * 256;
            int row = idx >> 3;          // 0..127
            int c4  = idx & 7;           // 0..7 -> k offset c4*4
            float4 a = make_float4(0.f, 0.f, 0.f, 0.f);
            if (m0 + row < M)
                a = *(const float4*)(A + (size_t)(m0 + row) * 128 + k0 + c4 * 4);
            As[row][c4 * 4 + 0] = a.x;
            As[row][c4 * 4 + 1] = a.y;
            As[row][c4 * 4 + 2] = a.z;
            As[row][c4 * 4 + 3] = a.w;
        }
        // load B tile 32x128
        #pragma unroll
        for (int it = 0; it < 4; it++) {
            int idx = tid + it * 256;
            int row = idx >> 5;          // 0..31
            int c4  = idx & 31;          // 0..31
            float4 b = *(const float4*)(B + (size_t)(k0 + row) * N + n0 + c4 * 4);
            *(float4*)&Bs[row][c4 * 4] = b;
        }
        __syncthreads();

        #pragma unroll
        for (int k = 0; k < 32; k++) {
            float a[8], b[8];
            #pragma unroll
            for (int i = 0; i < 8; i++) a[i] = As[ty * 8 + i][k];
            *(float4*)&b[0] = *(float4*)&Bs[k][tx * 8];
            *(float4*)&b[4] = *(float4*)&Bs[k][tx * 8 + 4];
            #pragma unroll
            for (int i = 0; i < 8; i++)
                #pragma unroll
                for (int j = 0; j < 8; j++) acc[i][j] += a[i] * b[j];
        }
        __syncthreads();
    }

    #pragma unroll
    for (int i = 0; i < 8; i++) {
        int m = m0 + ty * 8 + i;
        if (m >= M) break;
        #pragma unroll
        for (int j = 0; j < 8; j += 4) {
            int n = n0 + tx * 8 + j;
            float4 o;
            o.x = acc[i][j + 0] + bias[n + 0];
            o.y = acc[i][j + 1] + bias[n + 1];
            o.z = acc[i][j + 2] + bias[n + 2];
            o.w = acc[i][j + 3] + bias[n + 3];
            *(float4*)(C + (size_t)m * N + n) = o;
        }
    }
}

// ---------------- counting sort by dst ----------------
__global__ void zero_cnt_kernel() {
    int i = blockIdx.x * blockDim.x + threadIdx.x;
    if (i < N_NODES) g_cnt[i] = 0;
}

__global__ void hist_kernel(const int* __restrict__ dst) {
    int e = blockIdx.x * blockDim.x + threadIdx.x;
    if (e < N_EDGES) atomicAdd(&g_cnt[dst[e]], 1);
}

__global__ void scan_kernel() {
    __shared__ int warp_sums[32];
    __shared__ int s_off;
    const int t = threadIdx.x;
    const int lane = t & 31, wid = t >> 5;
    if (t == 0) s_off = 0;
    __syncthreads();
    for (int base = 0; base < N_NODES; base += 1024) {
        int i = base + t;
        int v = (i < N_NODES) ? g_cnt[i] : 0;
        // warp inclusive scan
        int x = v;
        #pragma unroll
        for (int d = 1; d < 32; d <<= 1) {
            int y = __shfl_up_sync(0xffffffffu, x, d);
            if (lane >= d) x += y;
        }
        if (lane == 31) warp_sums[wid] = x;
        __syncthreads();
        if (wid == 0) {
            int s = warp_sums[lane];
            #pragma unroll
            for (int d = 1; d < 32; d <<= 1) {
                int y = __shfl_up_sync(0xffffffffu, s, d);
                if (lane >= d) s += y;
            }
            warp_sums[lane] = s;
        }
        __syncthreads();
        int warp_off = (wid > 0) ? warp_sums[wid - 1] : 0;
        int inc = x + warp_off;
        int total = warp_sums[31];
        int excl = s_off + inc - v;
        if (i < N_NODES) { g_start[i] = excl; g_fill[i] = excl; }
        __syncthreads();
        if (t == 0) s_off += total;
        __syncthreads();
    }
    if (t == 0) g_start[N_NODES] = s_off;
}

__global__ void scatter_kernel(const int* __restrict__ src,
                               const int* __restrict__ dst,
                               const int* __restrict__ typ) {
    int e = blockIdx.x * blockDim.x + threadIdx.x;
    if (e >= N_EDGES) return;
    int d = dst[e];
    int pos = atomicAdd(&g_fill[d], 1);
    g_sorted[pos] = make_int2(src[e], typ[e]);
}

// ---------------- warp-per-dst softmax aggregation ----------------
// lane l owns dims [4l, 4l+4); head = l/4; per-head dot via shfl_xor over 4 lanes.
__global__ void agg_kernel(const float* __restrict__ rel) {
    int warp = (blockIdx.x * blockDim.x + threadIdx.x) >> 5;
    int lane = threadIdx.x & 31;
    if (warp >= N_NODES) return;
    const int dst = warp;
    const float4* __restrict__ QKV4 = (const float4*)g_QKV;  // stride 96 float4 per node
    const float4* __restrict__ R4   = (const float4*)rel;    // stride 32 float4 per rel

    float4 qv = QKV4[(size_t)dst * 96 + lane];
    int beg = g_start[dst], end = g_start[dst + 1];

    float4 acc = make_float4(0.f, 0.f, 0.f, 0.f);
    float sacc = 0.f;

    for (int e0 = beg; e0 < end; e0 += 32) {
        int2 er = make_int2(0, 0);
        if (e0 + lane < end) er = g_sorted[e0 + lane];
        int cnt = min(32, end - e0);
        for (int i = 0; i < cnt; i++) {
            int src = __shfl_sync(0xffffffffu, er.x, i);
            int typ = __shfl_sync(0xffffffffu, er.y, i);
            float4 kv = QKV4[(size_t)src * 96 + 32 + lane];
            float4 rb = R4[typ * 32 + lane];
            float p = qv.x * (kv.x + rb.x) + qv.y * (kv.y + rb.y)
                    + qv.z * (kv.z + rb.z) + qv.w * (kv.w + rb.w);
            p += __shfl_xor_sync(0xffffffffu, p, 1);
            p += __shfl_xor_sync(0xffffffffu, p, 2);   // full 16-dim head dot
            float w = __expf(p * 0.25f);               // 1/SCALE = 1/4
            float4 vv = QKV4[(size_t)src * 96 + 64 + lane];
            sacc += w;
            acc.x += w * vv.x; acc.y += w * vv.y;
            acc.z += w * vv.z; acc.w += w * vv.w;
        }
    }
    float inv = 1.0f / (sacc + 1e-8f);
    float4 o = make_float4(acc.x * inv, acc.y * inv, acc.z * inv, acc.w * inv);
    ((float4*)g_AO)[(size_t)dst * 32 + lane] = o;
}

// ---------------- launch ----------------
extern "C" void kernel_launch(void* const* d_in, const int* in_sizes, int n_in,
                              void* d_out, int out_size) {
    const float* node_features = (const float*)d_in[0];
    const float* query_emb     = (const float*)d_in[1];
    const float* rel_emb       = (const float*)d_in[2];
    const float* Wq            = (const float*)d_in[3];
    const float* bq            = (const float*)d_in[4];
    const float* Wk            = (const float*)d_in[5];
    const float* bk            = (const float*)d_in[6];
    const float* Wv            = (const float*)d_in[7];
    const float* bv            = (const float*)d_in[8];
    const float* Wo            = (const float*)d_in[9];
    const float* bo            = (const float*)d_in[10];
    const int*   edge_index    = (const int*)d_in[11];   // int32: JAX default x64-disabled
    const int*   edge_type     = (const int*)d_in[12];
    float* out = (float*)d_out;

    const int* e_src = edge_index;
    const int* e_dst = edge_index + N_EDGES;

    float* d_QKV; cudaGetSymbolAddress((void**)&d_QKV, g_QKV);
    float* d_AO;  cudaGetSymbolAddress((void**)&d_AO,  g_AO);
    float* d_Bp;  cudaGetSymbolAddress((void**)&d_Bp,  g_Bpack);
    float* d_bp;  cudaGetSymbolAddress((void**)&d_bp,  g_biasp);

    prep_kernel<<<1, 384>>>(query_emb, Wq, bq, Wk, bk, Wv, bv);
    zero_cnt_kernel<<<(N_NODES + 255) / 256, 256>>>();

    // fused QKV projection: 50000x384
    {
        dim3 grid((N_NODES + 127) / 128, 3);
        gemm_kernel<<<grid, 256>>>(node_features, d_Bp, d_bp, d_QKV, N_NODES, 384);
    }

    hist_kernel<<<(N_EDGES + 255) / 256, 256>>>(e_dst);
    scan_kernel<<<1, 1024>>>();
    scatter_kernel<<<(N_EDGES + 255) / 256, 256>>>(e_src, e_dst, edge_type);

    agg_kernel<<<(N_NODES * 32 + 255) / 256, 256>>>(rel_emb);

    // output projection: 50000x128 @ 128x128 + bo
    {
        dim3 grid((N_NODES + 127) / 128, 1);
        gemm_kernel<<<grid, 256>>>(d_AO, Wo, bo, out, N_NODES, 128);
    }
}

// round 5
// speedup vs baseline: 1.0507x; 1.0507x over previous
#include <cuda_runtime.h>
#include <cuda_bf16.h>
#include <math.h>

#define N_NODES 50000
#define N_EDGES 800000
#define HIDDEN  128
#define N_REL   64

// ---------------- device scratch (no dynamic allocation allowed) ----------------
__device__ float g_QKV[N_NODES * 384];     // q | k | v per node, stride 384
__device__ float g_AO[N_NODES * HIDDEN];   // attention output before Wo
__device__ float g_Bpack[128 * 384];       // [Wq_top | Wk_top | Wv]
__device__ float g_biasp[384];             // [cq | ck | bv]
__device__ int   g_cnt[N_NODES];
__device__ int   g_start[N_NODES + 1];
__device__ int   g_fill[N_NODES];
__device__ int2  g_sorted[N_EDGES];        // (src, type) sorted by dst

// ---------------- pack B: coalesced, grid-wide ----------------
__global__ void pack_kernel(const float* __restrict__ Wq,
                            const float* __restrict__ Wk,
                            const float* __restrict__ Wv) {
    int idx = blockIdx.x * blockDim.x + threadIdx.x;
    if (idx >= 128 * 384) return;
    int i = idx / 384, j = idx - i * 384;
    float v;
    if (j < 128)      v = Wq[i * 128 + j];
    else if (j < 256) v = Wk[i * 128 + (j - 128)];
    else              v = Wv[i * 128 + (j - 256)];
    g_Bpack[idx] = v;
}

// ---------------- bias: fold query into q/k biases ----------------
__global__ void bias_kernel(const float* __restrict__ qe,
                            const float* __restrict__ Wq, const float* __restrict__ bq,
                            const float* __restrict__ Wk, const float* __restrict__ bk,
                            const float* __restrict__ bv) {
    __shared__ float qs[128];
    int j = threadIdx.x;
    qs[j] = qe[j];
    __syncthreads();
    int b = blockIdx.x;
    if (b == 0) {
        float c = bq[j];
        #pragma unroll 4
        for (int i = 0; i < 128; i++) c += qs[i] * Wq[(128 + i) * 128 + j];
        g_biasp[j] = c;
    } else if (b == 1) {
        float c = bk[j];
        #pragma unroll 4
        for (int i = 0; i < 128; i++) c += qs[i] * Wk[(128 + i) * 128 + j];
        g_biasp[128 + j] = c;
    } else {
        g_biasp[256 + j] = bv[j];
    }
}

// ---------------- fp32 GEMM with packed f32x2 FMA ----------------
// C[M,N] = A[M,128] @ B[128,N] + bias. BM=128, BN=128, BK=32, 256 threads,
// 8 rows x 8 cols (= 4 packed pairs) per thread. FFMA2 doubles fma-pipe flops.
__global__ void gemm_kernel(const float* __restrict__ A, const float* __restrict__ B,
                            const float* __restrict__ bias, float* __restrict__ C,
                            int M, int N) {
    __shared__ float As[128][33];   // [m][k], padded
    __shared__ float Bs[32][128];   // [k][n]
    const int tid = threadIdx.x;
    const int tx = tid & 15;        // 0..15 -> 8 cols
    const int ty = tid >> 4;        // 0..15 -> 8 rows
    const int m0 = blockIdx.x * 128;
    const int n0 = blockIdx.y * 128;

    unsigned long long acc[8][4];   // 8 rows x 4 packed f32x2 col-pairs
    #pragma unroll
    for (int i = 0; i < 8; i++)
        #pragma unroll
        for (int j = 0; j < 4; j++) acc[i][j] = 0ull;

    for (int k0 = 0; k0 < 128; k0 += 32) {
        // load A tile 128x32 (float4, coalesced) -> As[m][k]
        #pragma unroll
        for (int it = 0; it < 4; it++) {
            int idx = tid + it * 256;
            int row = idx >> 3;          // 0..127
            int c4  = idx & 7;           // k offset c4*4
            float4 a = make_float4(0.f, 0.f, 0.f, 0.f);
            if (m0 + row < M)
                a = *(const float4*)(A + (size_t)(m0 + row) * 128 + k0 + c4 * 4);
            As[row][c4 * 4 + 0] = a.x;
            As[row][c4 * 4 + 1] = a.y;
            As[row][c4 * 4 + 2] = a.z;
            As[row][c4 * 4 + 3] = a.w;
        }
        // load B tile 32x128
        #pragma unroll
        for (int it = 0; it < 4; it++) {
            int idx = tid + it * 256;
            int row = idx >> 5;
            int c4  = idx & 31;
            float4 b = *(const float4*)(B + (size_t)(k0 + row) * N + n0 + c4 * 4);
            *(float4*)&Bs[row][c4 * 4] = b;
        }
        __syncthreads();

        #pragma unroll
        for (int k = 0; k < 32; k++) {
            // broadcast-pack a[i] into both halves of a 64-bit pair
            unsigned long long ap[8];
            #pragma unroll
            for (int i = 0; i < 8; i++) {
                unsigned int au = __float_as_uint(As[ty * 8 + i][k]);
                asm("mov.b64 %0, {%1, %1};" : "=l"(ap[i]) : "r"(au));
            }
            // b col-pairs: 8 consecutive floats = 4 packed pairs
            unsigned long long bp[4];
            ulonglong2 b01 = *(const ulonglong2*)&Bs[k][tx * 8];
            ulonglong2 b23 = *(const ulonglong2*)&Bs[k][tx * 8 + 4];
            bp[0] = b01.x; bp[1] = b01.y; bp[2] = b23.x; bp[3] = b23.y;
            #pragma unroll
            for (int i = 0; i < 8; i++)
                #pragma unroll
                for (int j = 0; j < 4; j++)
                    asm("fma.rn.f32x2 %0, %1, %2, %0;"
                        : "+l"(acc[i][j]) : "l"(ap[i]), "l"(bp[j]));
        }
        __syncthreads();
    }

    #pragma unroll
    for (int i = 0; i < 8; i++) {
        int m = m0 + ty * 8 + i;
        if (m >= M) break;
        #pragma unroll
        for (int j = 0; j < 4; j += 2) {
            int n = n0 + tx * 8 + j * 2;
            float2 p0 = *(float2*)&acc[i][j];
            float2 p1 = *(float2*)&acc[i][j + 1];
            float4 o;
            o.x = p0.x + bias[n + 0];
            o.y = p0.y + bias[n + 1];
            o.z = p1.x + bias[n + 2];
            o.w = p1.y + bias[n + 3];
            *(float4*)(C + (size_t)m * N + n) = o;
        }
    }
}

// ---------------- counting sort by dst ----------------
__global__ void zero_cnt_kernel() {
    int i = blockIdx.x * blockDim.x + threadIdx.x;
    if (i < N_NODES) g_cnt[i] = 0;
}

__global__ void hist_kernel(const int* __restrict__ dst) {
    int e = blockIdx.x * blockDim.x + threadIdx.x;
    if (e < N_EDGES) atomicAdd(&g_cnt[dst[e]], 1);
}

__global__ void scan_kernel() {
    __shared__ int warp_sums[32];
    __shared__ int s_off;
    const int t = threadIdx.x;
    const int lane = t & 31, wid = t >> 5;
    if (t == 0) s_off = 0;
    __syncthreads();
    for (int base = 0; base < N_NODES; base += 1024) {
        int i = base + t;
        int v = (i < N_NODES) ? g_cnt[i] : 0;
        int x = v;
        #pragma unroll
        for (int d = 1; d < 32; d <<= 1) {
            int y = __shfl_up_sync(0xffffffffu, x, d);
            if (lane >= d) x += y;
        }
        if (lane == 31) warp_sums[wid] = x;
        __syncthreads();
        if (wid == 0) {
            int s = warp_sums[lane];
            #pragma unroll
            for (int d = 1; d < 32; d <<= 1) {
                int y = __shfl_up_sync(0xffffffffu, s, d);
                if (lane >= d) s += y;
            }
            warp_sums[lane] = s;
        }
        __syncthreads();
        int warp_off = (wid > 0) ? warp_sums[wid - 1] : 0;
        int inc = x + warp_off;
        int total = warp_sums[31];
        int excl = s_off + inc - v;
        if (i < N_NODES) { g_start[i] = excl; g_fill[i] = excl; }
        __syncthreads();
        if (t == 0) s_off += total;
        __syncthreads();
    }
    if (t == 0) g_start[N_NODES] = s_off;
}

__global__ void scatter_kernel(const int* __restrict__ src,
                               const int* __restrict__ dst,
                               const int* __restrict__ typ) {
    int e = blockIdx.x * blockDim.x + threadIdx.x;
    if (e >= N_EDGES) return;
    int d = dst[e];
    int pos = atomicAdd(&g_fill[d], 1);
    g_sorted[pos] = make_int2(src[e], typ[e]);
}

// ---------------- warp-per-dst softmax aggregation ----------------
// lane l owns dims [4l, 4l+4); head = l/4; per-head dot via shfl_xor over 4 lanes.
__global__ void agg_kernel(const float* __restrict__ rel) {
    int warp = (blockIdx.x * blockDim.x + threadIdx.x) >> 5;
    int lane = threadIdx.x & 31;
    if (warp >= N_NODES) return;
    const int dst = warp;
    const float4* __restrict__ QKV4 = (const float4*)g_QKV;  // stride 96 float4/node
    const float4* __restrict__ R4   = (const float4*)rel;    // stride 32 float4/rel

    float4 qv = QKV4[(size_t)dst * 96 + lane];
    int beg = g_start[dst], end = g_start[dst + 1];

    float4 acc = make_float4(0.f, 0.f, 0.f, 0.f);
    float sacc = 0.f;

    for (int e0 = beg; e0 < end; e0 += 32) {
        int2 er = make_int2(0, 0);
        if (e0 + lane < end) er = g_sorted[e0 + lane];
        int cnt = min(32, end - e0);
        if (cnt == 32) {
            #pragma unroll 4
            for (int i = 0; i < 32; i++) {
                int src = __shfl_sync(0xffffffffu, er.x, i);
                int typ = __shfl_sync(0xffffffffu, er.y, i);
                float4 kv = QKV4[(size_t)src * 96 + 32 + lane];
                float4 vv = QKV4[(size_t)src * 96 + 64 + lane];
                float4 rb = R4[typ * 32 + lane];
                float p = qv.x * (kv.x + rb.x) + qv.y * (kv.y + rb.y)
                        + qv.z * (kv.z + rb.z) + qv.w * (kv.w + rb.w);
                p += __shfl_xor_sync(0xffffffffu, p, 1);
                p += __shfl_xor_sync(0xffffffffu, p, 2);
                float w = __expf(p * 0.25f);
                sacc += w;
                acc.x += w * vv.x; acc.y += w * vv.y;
                acc.z += w * vv.z; acc.w += w * vv.w;
            }
        } else {
            for (int i = 0; i < cnt; i++) {
                int src = __shfl_sync(0xffffffffu, er.x, i);
                int typ = __shfl_sync(0xffffffffu, er.y, i);
                float4 kv = QKV4[(size_t)src * 96 + 32 + lane];
                float4 vv = QKV4[(size_t)src * 96 + 64 + lane];
                float4 rb = R4[typ * 32 + lane];
                float p = qv.x * (kv.x + rb.x) + qv.y * (kv.y + rb.y)
                        + qv.z * (kv.z + rb.z) + qv.w * (kv.w + rb.w);
                p += __shfl_xor_sync(0xffffffffu, p, 1);
                p += __shfl_xor_sync(0xffffffffu, p, 2);
                float w = __expf(p * 0.25f);
                sacc += w;
                acc.x += w * vv.x; acc.y += w * vv.y;
                acc.z += w * vv.z; acc.w += w * vv.w;
            }
        }
    }
    float inv = 1.0f / (sacc + 1e-8f);
    float4 o = make_float4(acc.x * inv, acc.y * inv, acc.z * inv, acc.w * inv);
    ((float4*)g_AO)[(size_t)dst * 32 + lane] = o;
}

// ---------------- launch ----------------
extern "C" void kernel_launch(void* const* d_in, const int* in_sizes, int n_in,
                              void* d_out, int out_size) {
    const float* node_features = (const float*)d_in[0];
    const float* query_emb     = (const float*)d_in[1];
    const float* rel_emb       = (const float*)d_in[2];
    const float* Wq            = (const float*)d_in[3];
    const float* bq            = (const float*)d_in[4];
    const float* Wk            = (const float*)d_in[5];
    const float* bk            = (const float*)d_in[6];
    const float* Wv            = (const float*)d_in[7];
    const float* bv            = (const float*)d_in[8];
    const float* Wo            = (const float*)d_in[9];
    const float* bo            = (const float*)d_in[10];
    const int*   edge_index    = (const int*)d_in[11];
    const int*   edge_type     = (const int*)d_in[12];
    float* out = (float*)d_out;

    const int* e_src = edge_index;
    const int* e_dst = edge_index + N_EDGES;

    float* d_QKV; cudaGetSymbolAddress((void**)&d_QKV, g_QKV);
    float* d_AO;  cudaGetSymbolAddress((void**)&d_AO,  g_AO);
    float* d_Bp;  cudaGetSymbolAddress((void**)&d_Bp,  g_Bpack);
    float* d_bp;  cudaGetSymbolAddress((void**)&d_bp,  g_biasp);

    pack_kernel<<<(128 * 384 + 255) / 256, 256>>>(Wq, Wk, Wv);
    bias_kernel<<<3, 128>>>(query_emb, Wq, bq, Wk, bk, bv);
    zero_cnt_kernel<<<(N_NODES + 255) / 256, 256>>>();

    // fused QKV projection: 50000x384
    {
        dim3 grid((N_NODES + 127) / 128, 3);
        gemm_kernel<<<grid, 256>>>(node_features, d_Bp, d_bp, d_QKV, N_NODES, 384);
    }

    hist_kernel<<<(N_EDGES + 255) / 256, 256>>>(e_dst);
    scan_kernel<<<1, 1024>>>();
    scatter_kernel<<<(N_EDGES + 255) / 256, 256>>>(e_src, e_dst, edge_type);

    agg_kernel<<<(N_NODES * 32 + 255) / 256, 256>>>(rel_emb);

    // output projection: 50000x128 @ 128x128 + bo
    {
        dim3 grid((N_NODES + 127) / 128, 1);
        gemm_kernel<<<grid, 256>>>(d_AO, Wo, bo, out, N_NODES, 128);
    }
}